// round 2
// baseline (speedup 1.0000x reference)
#include <cuda_runtime.h>
#include <cuda_fp16.h>
#include <cstdint>

// ---------------- problem geometry ----------------
static constexpr int MDIM = 8192;
static constexpr int NDIM = 4096;
static constexpr int KDIM = 4096;

static constexpr int BM = 128;
static constexpr int BN = 128;
static constexpr int BKC = 32;               // fp16 k elems per chunk (64 B)
static constexpr int NKC = KDIM / BKC;       // 128 chunks
static constexpr int STAGES = 4;

static constexpr int ROW_HALFS = 40;         // 32 + 8 pad -> 80 B row stride
static constexpr int TILE_B = BM * ROW_HALFS * 2;        // 10240 bytes per tile buffer
static constexpr int STAGE_B = 3 * TILE_B;               // Ahi + Alo + B
static constexpr int SMEM_BYTES = STAGES * STAGE_B;      // 122880

// ---------------- device scratch (allocation-free) ----------------
static __device__ __half g_xhi[(size_t)MDIM * KDIM];
static __device__ __half g_xlo[(size_t)MDIM * KDIM];
static __device__ __half g_whi[(size_t)NDIM * KDIM];

// ---------------- PTX helpers (all base-target, sm_80-era) ----------------
__device__ __forceinline__ uint32_t smem_u32(const void* p) {
    uint32_t a;
    asm("{ .reg .u64 t; cvta.to.shared.u64 t, %1; cvt.u32.u64 %0, t; }" : "=r"(a) : "l"(p));
    return a;
}

#define CP_ASYNC16(dst, src) \
    asm volatile("cp.async.cg.shared.global [%0], [%1], 16;" :: "r"(dst), "l"(src) : "memory")
#define CP_COMMIT() asm volatile("cp.async.commit_group;" ::: "memory")
#define CP_WAIT(n)  asm volatile("cp.async.wait_group %0;" :: "n"(n) : "memory")

#define LDSM4(r0, r1, r2, r3, addr)                                        \
    asm volatile("ldmatrix.sync.aligned.m8n8.x4.shared.b16 {%0,%1,%2,%3}, [%4];" \
                 : "=r"(r0), "=r"(r1), "=r"(r2), "=r"(r3) : "r"(addr))

#define MMA16816(c, a, b0, b1)                                             \
    asm volatile(                                                          \
        "mma.sync.aligned.m16n8k16.row.col.f32.f16.f16.f32 "               \
        "{%0,%1,%2,%3}, {%4,%5,%6,%7}, {%8,%9}, {%0,%1,%2,%3};"            \
        : "+f"((c)[0]), "+f"((c)[1]), "+f"((c)[2]), "+f"((c)[3])           \
        : "r"((a)[0]), "r"((a)[1]), "r"((a)[2]), "r"((a)[3]),              \
          "r"(b0), "r"(b1))

// ---------------- conversion kernels ----------------
__global__ void __launch_bounds__(256) k_split_x(const float* __restrict__ src,
                                                 __half* __restrict__ hi,
                                                 __half* __restrict__ lo,
                                                 int n4) {
    int i = blockIdx.x * blockDim.x + threadIdx.x;
    if (i >= n4) return;
    float4 v = reinterpret_cast<const float4*>(src)[i];
    __half h0 = __float2half_rn(v.x);
    __half h1 = __float2half_rn(v.y);
    __half h2 = __float2half_rn(v.z);
    __half h3 = __float2half_rn(v.w);
    __half l0 = __float2half_rn(v.x - __half2float(h0));
    __half l1 = __float2half_rn(v.y - __half2float(h1));
    __half l2 = __float2half_rn(v.z - __half2float(h2));
    __half l3 = __float2half_rn(v.w - __half2float(h3));
    __half2 hp0(h0, h1), hp1(h2, h3), lp0(l0, l1), lp1(l2, l3);
    uint2 ho, lu;
    ho.x = *reinterpret_cast<uint32_t*>(&hp0);
    ho.y = *reinterpret_cast<uint32_t*>(&hp1);
    lu.x = *reinterpret_cast<uint32_t*>(&lp0);
    lu.y = *reinterpret_cast<uint32_t*>(&lp1);
    reinterpret_cast<uint2*>(hi)[i] = ho;
    reinterpret_cast<uint2*>(lo)[i] = lu;
}

__global__ void __launch_bounds__(256) k_cvt_w(const float* __restrict__ src,
                                               __half* __restrict__ dst, int n4) {
    int i = blockIdx.x * blockDim.x + threadIdx.x;
    if (i >= n4) return;
    float4 v = reinterpret_cast<const float4*>(src)[i];
    __half2 p0(__float2half_rn(v.x), __float2half_rn(v.y));
    __half2 p1(__float2half_rn(v.z), __float2half_rn(v.w));
    uint2 o;
    o.x = *reinterpret_cast<uint32_t*>(&p0);
    o.y = *reinterpret_cast<uint32_t*>(&p1);
    reinterpret_cast<uint2*>(dst)[i] = o;
}

// ---------------- GEMM: y = (xhi + xlo) @ whi^T + bias ----------------
__global__ void __launch_bounds__(256, 1) k_gemm(
    const __half* __restrict__ xhi, const __half* __restrict__ xlo,
    const __half* __restrict__ whi, const float* __restrict__ bias,
    float* __restrict__ out) {
    extern __shared__ char smem[];
    const uint32_t sb = smem_u32(smem);

    const int tid = threadIdx.x;
    const int wid = tid >> 5;
    const int lane = tid & 31;
    const int warp_m = wid & 1;   // 0..1 (64 rows each)
    const int warp_n = wid >> 1;  // 0..3 (32 cols each)

    // tile mapping with L2 supergrouping
    constexpr int NPN = NDIM / BN;  // 32
    constexpr int GROUP_M = 8;
    int pid = blockIdx.x;
    int npg = GROUP_M * NPN;  // 256
    int pm = (pid / npg) * GROUP_M + (pid % npg) % GROUP_M;
    int pn = (pid % npg) / GROUP_M;

    const int ldrow = tid >> 2;   // 0..63
    const int ldseg = tid & 3;    // 0..3

    // per-stage smem buffer bases
    auto ahi_s = [&](int s) { return sb + (uint32_t)s * STAGE_B; };
    auto alo_s = [&](int s) { return sb + (uint32_t)s * STAGE_B + TILE_B; };
    auto bs_s  = [&](int s) { return sb + (uint32_t)s * STAGE_B + 2 * TILE_B; };

    const __half* gA_hi = xhi + (size_t)(pm * BM) * KDIM;
    const __half* gA_lo = xlo + (size_t)(pm * BM) * KDIM;
    const __half* gB    = whi + (size_t)(pn * BN) * KDIM;

    auto issue_stage = [&](int it, int buf) {
        if (it < NKC) {
            int k0 = it * BKC;
            uint32_t dsta = ahi_s(buf), dstl = alo_s(buf), dstb = bs_s(buf);
            #pragma unroll
            for (int r0 = 0; r0 < BM; r0 += 64) {
                int r = r0 + ldrow;
                uint32_t doff = (uint32_t)(r * (ROW_HALFS * 2) + ldseg * 16);
                size_t goff = (size_t)r * KDIM + k0 + ldseg * 8;
                CP_ASYNC16(dsta + doff, gA_hi + goff);
                CP_ASYNC16(dstl + doff, gA_lo + goff);
                CP_ASYNC16(dstb + doff, gB + goff);
            }
        }
        CP_COMMIT();
    };

    // ldmatrix per-lane offsets (bytes)
    // A: row = lane%16, koff = (lane/16)*8 halfs
    const uint32_t a_lane = (uint32_t)((lane & 15) * (ROW_HALFS * 2) + (lane >> 4) * 16);
    // B: mat = lane/8, row = lane%8; n = (mat>>1)*8 + row, koff = (mat&1)*8 halfs
    const uint32_t b_lane = (uint32_t)((((lane >> 4) * 8) + (lane & 7)) * (ROW_HALFS * 2) +
                                       (((lane >> 3) & 1) * 16));
    const uint32_t a_warp = (uint32_t)(warp_m * 64 * (ROW_HALFS * 2));
    const uint32_t b_warp = (uint32_t)(warp_n * 32 * (ROW_HALFS * 2));

    float acc[4][4][4];
    #pragma unroll
    for (int i = 0; i < 4; i++)
        #pragma unroll
        for (int j = 0; j < 4; j++)
            #pragma unroll
            for (int t = 0; t < 4; t++) acc[i][j][t] = 0.0f;

    // prologue: fill STAGES-1 stages
    #pragma unroll
    for (int s = 0; s < STAGES - 1; s++) issue_stage(s, s);

    for (int it = 0; it < NKC; ++it) {
        CP_WAIT(STAGES - 2);
        __syncthreads();

        issue_stage(it + STAGES - 1, (it + STAGES - 1) % STAGES);

        int buf = it % STAGES;
        uint32_t Ah = ahi_s(buf) + a_warp;
        uint32_t Al = alo_s(buf) + a_warp;
        uint32_t Bb = bs_s(buf) + b_warp;

        #pragma unroll
        for (int ks = 0; ks < 2; ks++) {
            uint32_t koffb = (uint32_t)(ks * 32);
            uint32_t br[2][4];
            #pragma unroll
            for (int p = 0; p < 2; p++)
                LDSM4(br[p][0], br[p][1], br[p][2], br[p][3],
                      Bb + (uint32_t)(p * 16 * (ROW_HALFS * 2)) + koffb + b_lane);

            uint32_t ah[4][4], al[4][4];
            #pragma unroll
            for (int ms = 0; ms < 4; ms++) {
                uint32_t off = (uint32_t)(ms * 16 * (ROW_HALFS * 2)) + koffb + a_lane;
                LDSM4(ah[ms][0], ah[ms][1], ah[ms][2], ah[ms][3], Ah + off);
                LDSM4(al[ms][0], al[ms][1], al[ms][2], al[ms][3], Al + off);
            }

            #pragma unroll
            for (int ms = 0; ms < 4; ms++) {
                #pragma unroll
                for (int ns = 0; ns < 4; ns++) {
                    MMA16816(acc[ms][ns], ah[ms], br[ns >> 1][(ns & 1) * 2],
                             br[ns >> 1][(ns & 1) * 2 + 1]);
                }
                #pragma unroll
                for (int ns = 0; ns < 4; ns++) {
                    MMA16816(acc[ms][ns], al[ms], br[ns >> 1][(ns & 1) * 2],
                             br[ns >> 1][(ns & 1) * 2 + 1]);
                }
            }
        }
    }

    // epilogue: acc + bias -> out
    const int m_base = pm * BM + warp_m * 64 + (lane >> 2);
    const int n_base = pn * BN + warp_n * 32 + (lane & 3) * 2;
    #pragma unroll
    for (int ns = 0; ns < 4; ns++) {
        int col = n_base + ns * 8;
        float bv0 = __ldg(&bias[col]);
        float bv1 = __ldg(&bias[col + 1]);
        #pragma unroll
        for (int ms = 0; ms < 4; ms++) {
            int r0 = m_base + ms * 16;
            float2 v0, v1;
            v0.x = acc[ms][ns][0] + bv0;
            v0.y = acc[ms][ns][1] + bv1;
            v1.x = acc[ms][ns][2] + bv0;
            v1.y = acc[ms][ns][3] + bv1;
            *reinterpret_cast<float2*>(out + (size_t)r0 * NDIM + col) = v0;
            *reinterpret_cast<float2*>(out + (size_t)(r0 + 8) * NDIM + col) = v1;
        }
    }
}

// ---------------- host side ----------------
extern "C" void kernel_launch(void* const* d_in, const int* in_sizes, int n_in,
                              void* d_out, int out_size) {
    const float* x    = (const float*)d_in[0];
    const float* w    = (const float*)d_in[1];
    const float* bias = (const float*)d_in[2];
    float* out        = (float*)d_out;

    void *p_xhi, *p_xlo, *p_whi;
    cudaGetSymbolAddress(&p_xhi, g_xhi);
    cudaGetSymbolAddress(&p_xlo, g_xlo);
    cudaGetSymbolAddress(&p_whi, g_whi);

    int n4x = MDIM * KDIM / 4;
    int n4w = NDIM * KDIM / 4;
    k_split_x<<<(n4x + 255) / 256, 256>>>(x, (__half*)p_xhi, (__half*)p_xlo, n4x);
    k_cvt_w<<<(n4w + 255) / 256, 256>>>(w, (__half*)p_whi, n4w);

    static bool attr_set = false;
    if (!attr_set) {
        cudaFuncSetAttribute(k_gemm, cudaFuncAttributeMaxDynamicSharedMemorySize, SMEM_BYTES);
        attr_set = true;
    }

    int grid = (MDIM / BM) * (NDIM / BN);  // 2048
    k_gemm<<<grid, 256, SMEM_BYTES>>>((const __half*)p_xhi, (const __half*)p_xlo,
                                      (const __half*)p_whi, bias, out);
}

// round 4
// speedup vs baseline: 1.7884x; 1.7884x over previous
#include <cuda_runtime.h>
#include <cuda_fp16.h>
#include <cstdint>

// ---------------- problem geometry ----------------
static constexpr int MDIM = 8192;
static constexpr int NDIM = 4096;
static constexpr int KDIM = 4096;

static constexpr int BM = 128;
static constexpr int BN = 256;
static constexpr int BKC = 32;               // fp16 k elems per chunk (64 B)
static constexpr int NKC = KDIM / BKC;       // 128 chunks
static constexpr int STAGES = 4;

static constexpr int ROW_HALFS = 40;         // 32 + 8 pad -> 80 B row stride
static constexpr int A_TILE_B = BM * ROW_HALFS * 2;      // 10240 bytes
static constexpr int B_TILE_B = BN * ROW_HALFS * 2;      // 20480 bytes
static constexpr int STAGE_B = A_TILE_B + B_TILE_B;      // 30720
static constexpr int SMEM_BYTES = STAGES * STAGE_B;      // 122880

// ---------------- device scratch (allocation-free) ----------------
static __device__ __half g_xh[(size_t)MDIM * KDIM];
static __device__ __half g_wh[(size_t)NDIM * KDIM];

// ---------------- PTX helpers (base-target, sm_80-era) ----------------
__device__ __forceinline__ uint32_t smem_u32(const void* p) {
    uint32_t a;
    asm("{ .reg .u64 t; cvta.to.shared.u64 t, %1; cvt.u32.u64 %0, t; }" : "=r"(a) : "l"(p));
    return a;
}

#define CP_ASYNC16(dst, src) \
    asm volatile("cp.async.cg.shared.global [%0], [%1], 16;" :: "r"(dst), "l"(src) : "memory")
#define CP_COMMIT() asm volatile("cp.async.commit_group;" ::: "memory")
#define CP_WAIT(n)  asm volatile("cp.async.wait_group %0;" :: "n"(n) : "memory")

#define LDSM4(r0, r1, r2, r3, addr)                                        \
    asm volatile("ldmatrix.sync.aligned.m8n8.x4.shared.b16 {%0,%1,%2,%3}, [%4];" \
                 : "=r"(r0), "=r"(r1), "=r"(r2), "=r"(r3) : "r"(addr))

#define MMA16816(c, a, b0, b1)                                             \
    asm volatile(                                                          \
        "mma.sync.aligned.m16n8k16.row.col.f32.f16.f16.f32 "               \
        "{%0,%1,%2,%3}, {%4,%5,%6,%7}, {%8,%9}, {%0,%1,%2,%3};"            \
        : "+f"((c)[0]), "+f"((c)[1]), "+f"((c)[2]), "+f"((c)[3])           \
        : "r"((a)[0]), "r"((a)[1]), "r"((a)[2]), "r"((a)[3]),              \
          "r"(b0), "r"(b1))

// ---------------- conversion kernel: fp32 -> fp16 ----------------
__global__ void __launch_bounds__(256) k_cvt(const float* __restrict__ src,
                                             __half* __restrict__ dst, int n4) {
    int i = blockIdx.x * blockDim.x + threadIdx.x;
    if (i >= n4) return;
    float4 v = reinterpret_cast<const float4*>(src)[i];
    __half2 p0(__float2half_rn(v.x), __float2half_rn(v.y));
    __half2 p1(__float2half_rn(v.z), __float2half_rn(v.w));
    uint2 o;
    o.x = *reinterpret_cast<uint32_t*>(&p0);
    o.y = *reinterpret_cast<uint32_t*>(&p1);
    reinterpret_cast<uint2*>(dst)[i] = o;
}

// ---------------- GEMM: y = xh @ wh^T + bias ----------------
__global__ void __launch_bounds__(256, 1) k_gemm(
    const __half* __restrict__ xh, const __half* __restrict__ wh,
    const float* __restrict__ bias, float* __restrict__ out) {
    extern __shared__ char smem[];
    const uint32_t sb = smem_u32(smem);

    const int tid = threadIdx.x;
    const int wid = tid >> 5;
    const int lane = tid & 31;
    const int warp_m = wid & 1;   // 0..1 -> 64 rows each
    const int warp_n = wid >> 1;  // 0..3 -> 64 cols each

    // tile mapping with L2 supergrouping
    constexpr int NPN = NDIM / BN;  // 16
    constexpr int GROUP_M = 8;
    int pid = blockIdx.x;
    int npg = GROUP_M * NPN;        // 128
    int pm = (pid / npg) * GROUP_M + (pid % npg) % GROUP_M;
    int pn = (pid % npg) / GROUP_M;

    const int ldrow = tid >> 2;   // 0..63
    const int ldseg = tid & 3;    // 0..3

    auto a_s = [&](int s) { return sb + (uint32_t)s * STAGE_B; };
    auto b_s = [&](int s) { return sb + (uint32_t)s * STAGE_B + A_TILE_B; };

    const __half* gA = xh + (size_t)(pm * BM) * KDIM;
    const __half* gB = wh + (size_t)(pn * BN) * KDIM;

    auto issue_stage = [&](int it, int buf) {
        if (it < NKC) {
            int k0 = it * BKC;
            uint32_t dsta = a_s(buf), dstb = b_s(buf);
            #pragma unroll
            for (int r0 = 0; r0 < BM; r0 += 64) {
                int r = r0 + ldrow;
                uint32_t doff = (uint32_t)(r * (ROW_HALFS * 2) + ldseg * 16);
                CP_ASYNC16(dsta + doff, gA + (size_t)r * KDIM + k0 + ldseg * 8);
            }
            #pragma unroll
            for (int r0 = 0; r0 < BN; r0 += 64) {
                int r = r0 + ldrow;
                uint32_t doff = (uint32_t)(r * (ROW_HALFS * 2) + ldseg * 16);
                CP_ASYNC16(dstb + doff, gB + (size_t)r * KDIM + k0 + ldseg * 8);
            }
        }
        CP_COMMIT();
    };

    // ldmatrix per-lane offsets (bytes)
    const uint32_t a_lane = (uint32_t)((lane & 15) * (ROW_HALFS * 2) + (lane >> 4) * 16);
    const uint32_t b_lane = (uint32_t)((((lane >> 4) * 8) + (lane & 7)) * (ROW_HALFS * 2) +
                                       (((lane >> 3) & 1) * 16));
    const uint32_t a_warp = (uint32_t)(warp_m * 64 * (ROW_HALFS * 2));
    const uint32_t b_warp = (uint32_t)(warp_n * 64 * (ROW_HALFS * 2));

    float acc[4][8][4];
    #pragma unroll
    for (int i = 0; i < 4; i++)
        #pragma unroll
        for (int j = 0; j < 8; j++)
            #pragma unroll
            for (int t = 0; t < 4; t++) acc[i][j][t] = 0.0f;

    #pragma unroll
    for (int s = 0; s < STAGES - 1; s++) issue_stage(s, s);

    for (int it = 0; it < NKC; ++it) {
        CP_WAIT(STAGES - 2);
        __syncthreads();

        issue_stage(it + STAGES - 1, (it + STAGES - 1) % STAGES);

        int buf = it % STAGES;
        uint32_t Ab = a_s(buf) + a_warp;
        uint32_t Bb = b_s(buf) + b_warp;

        #pragma unroll
        for (int ks = 0; ks < 2; ks++) {
            uint32_t koffb = (uint32_t)(ks * 32);

            uint32_t br[4][4];
            #pragma unroll
            for (int p = 0; p < 4; p++)
                LDSM4(br[p][0], br[p][1], br[p][2], br[p][3],
                      Bb + (uint32_t)(p * 16 * (ROW_HALFS * 2)) + koffb + b_lane);

            uint32_t ar[4][4];
            #pragma unroll
            for (int ms = 0; ms < 4; ms++)
                LDSM4(ar[ms][0], ar[ms][1], ar[ms][2], ar[ms][3],
                      Ab + (uint32_t)(ms * 16 * (ROW_HALFS * 2)) + koffb + a_lane);

            #pragma unroll
            for (int ms = 0; ms < 4; ms++)
                #pragma unroll
                for (int ns = 0; ns < 8; ns++)
                    MMA16816(acc[ms][ns], ar[ms], br[ns >> 1][(ns & 1) * 2],
                             br[ns >> 1][(ns & 1) * 2 + 1]);
        }
    }

    // epilogue: acc + bias -> out
    const int m_base = pm * BM + warp_m * 64 + (lane >> 2);
    const int n_base = pn * BN + warp_n * 64 + (lane & 3) * 2;
    #pragma unroll
    for (int ns = 0; ns < 8; ns++) {
        int col = n_base + ns * 8;
        float bv0 = __ldg(&bias[col]);
        float bv1 = __ldg(&bias[col + 1]);
        #pragma unroll
        for (int ms = 0; ms < 4; ms++) {
            int r0 = m_base + ms * 16;
            float2 v0, v1;
            v0.x = acc[ms][ns][0] + bv0;
            v0.y = acc[ms][ns][1] + bv1;
            v1.x = acc[ms][ns][2] + bv0;
            v1.y = acc[ms][ns][3] + bv1;
            *reinterpret_cast<float2*>(out + (size_t)r0 * NDIM + col) = v0;
            *reinterpret_cast<float2*>(out + (size_t)(r0 + 8) * NDIM + col) = v1;
        }
    }
}

// ---------------- host side ----------------
extern "C" void kernel_launch(void* const* d_in, const int* in_sizes, int n_in,
                              void* d_out, int out_size) {
    const float* x    = (const float*)d_in[0];
    const float* w    = (const float*)d_in[1];
    const float* bias = (const float*)d_in[2];
    float* out        = (float*)d_out;

    void *p_xh, *p_wh;
    cudaGetSymbolAddress(&p_xh, g_xh);
    cudaGetSymbolAddress(&p_wh, g_wh);

    int n4x = MDIM * KDIM / 4;
    int n4w = NDIM * KDIM / 4;
    k_cvt<<<(n4x + 255) / 256, 256>>>(x, (__half*)p_xh, n4x);
    k_cvt<<<(n4w + 255) / 256, 256>>>(w, (__half*)p_wh, n4w);

    static bool attr_set = false;
    if (!attr_set) {
        cudaFuncSetAttribute(k_gemm, cudaFuncAttributeMaxDynamicSharedMemorySize, SMEM_BYTES);
        attr_set = true;
    }

    int grid = (MDIM / BM) * (NDIM / BN);  // 1024
    k_gemm<<<grid, 256, SMEM_BYTES>>>((const __half*)p_xh, (const __half*)p_wh, bias, out);
}